// round 15
// baseline (speedup 1.0000x reference)
#include <cuda_runtime.h>
#include <cuda_fp16.h>
#include <cstdint>
#include <math.h>

// ---------------------------------------------------------------------------
// Problem constants
// ---------------------------------------------------------------------------
constexpr int Bc = 8;
constexpr int C  = 1024;
constexpr int Ci = 512;
constexpr int Nd = 48 * 48;          // 2304
constexpr int Na = 16 * 16;          // 256
constexpr int R  = 64;               // C / 16
constexpr float BN_INV = 0.9999950000374997f;  // 1/sqrt(1+1e-5)

// ---------------------------------------------------------------------------
// Device scratch (static); GEMM operands fp16 (same mantissa as tf32)
// ---------------------------------------------------------------------------
__device__ __half g_detT  [Bc * Nd * C];
__device__ __half g_aimT  [Bc * Na * C];
__device__ __half g_dx    [Bc * Ci * Nd];
__device__ __half g_phx   [Bc * Nd * Ci];
__device__ __half g_ax    [Bc * Ci * Na];
__device__ __half g_thx   [Bc * Na * Ci];
__device__ __half g_fm    [Bc * Na * Nd];
__device__ __half g_fT    [Bc * Nd * Na];
__device__ __half g_nap   [Bc * Na * Ci];
__device__ __half g_ndp   [Bc * Nd * Ci];
__device__ float  g_nonaim[Bc * C  * Na];
__device__ float  g_pooled[Bc * 2  * C];
__device__ __half g_gwr [Ci * C];
__device__ __half g_thwr[Ci * C];
__device__ __half g_phwr[Ci * C];
__device__ __half g_Wwr [C * Ci];
__device__ __half g_Qwr [C * Ci];

// ---------------------------------------------------------------------------
// helpers
// ---------------------------------------------------------------------------
__device__ __forceinline__ uint32_t smem_u32(const void* p) {
    uint32_t a;
    asm("{ .reg .u64 t; cvta.to.shared.u64 t, %1; cvt.u32.u64 %0, t; }" : "=r"(a) : "l"(p));
    return a;
}
__device__ __forceinline__ void mma16(float* d, const uint32_t* a, const uint32_t* b) {
    asm volatile(
        "mma.sync.aligned.m16n8k16.row.col.f32.f16.f16.f32 "
        "{%0,%1,%2,%3}, {%4,%5,%6,%7}, {%8,%9}, {%0,%1,%2,%3};"
        : "+f"(d[0]), "+f"(d[1]), "+f"(d[2]), "+f"(d[3])
        : "r"(a[0]), "r"(a[1]), "r"(a[2]), "r"(a[3]), "r"(b[0]), "r"(b[1]));
}
__device__ __forceinline__ void ldsm4(uint32_t* r, uint32_t a) {
    asm volatile("ldmatrix.sync.aligned.m8n8.x4.shared.b16 {%0,%1,%2,%3}, [%4];"
        : "=r"(r[0]), "=r"(r[1]), "=r"(r[2]), "=r"(r[3]) : "r"(a));
}
__device__ __forceinline__ void cpa16(uint32_t s, const void* g) {
    asm volatile("cp.async.cg.shared.global [%0], [%1], 16;" :: "r"(s), "l"(g));
}
#define CPA_COMMIT() asm volatile("cp.async.commit_group;" ::: "memory")
#define CPA_WAIT2()  asm volatile("cp.async.wait_group 2;" ::: "memory")

constexpr int SAB  = 48;               // smem row stride bytes (32 + 16)
constexpr int NSTG = 4;
constexpr int GS128 = NSTG * (128 + 128) * SAB;   // 49152 B
constexpr int GS64  = NSTG * (128 + 64)  * SAB;   // 36864 B

// ---------------------------------------------------------------------------
// Templated fp16 GEMM (R14-committed config) for G5 / G8 / G9.
//   D[M,N] = alpha*A[M,K]*B[N,K]^T; block 128xNB; warp tile 32x64; BK=16;
//   4-stage cp.async; ldmatrix.x4 fragments (R10/R14-verified mapping).
//   EPI 0: half out = alpha*acc
//   EPI 1: float out = bng[m]*BN_INV*(acc+bM[m]) + bnb[m] + resid
//   EPI 2: EPI1 + out2 = v * cw[bz*M + m]
// ---------------------------------------------------------------------------
template<int EPI, int NB>
__global__ void __launch_bounds__(NB * 2, (NB == 128) ? 2 : 3)
tgemm(const __half* __restrict__ A, const __half* __restrict__ B,
      void* __restrict__ Co,
      int K, int ldc, long strA, long strB, long strC, float alpha,
      const float* __restrict__ bM,
      const float* __restrict__ bng, const float* __restrict__ bnb,
      const float* __restrict__ resid, long sR,
      const float* __restrict__ cw, float* __restrict__ out2)
{
    constexpr int AWB    = 128 * SAB;
    constexpr int STAGEB = (128 + NB) * SAB;

    extern __shared__ uint32_t sm[];
    const uint32_t smb = smem_u32(sm);

    const int tid = threadIdx.x, lane = tid & 31, wid = tid >> 5;
    const int wm = wid & 3, wn = wid >> 2;
    const int bz = blockIdx.z;
    const int bm = blockIdx.y * 128, bn = blockIdx.x * NB;

    const __half* agp;  uint32_t asp;
    const __half* bgp = nullptr;  uint32_t bsp = 0;
    if constexpr (NB == 128) {
        const int lrow = tid & 127;
        const bool isA = tid < 128;
        agp = (isA ? A + (long)bz * strA + (long)(bm + lrow) * K
                   : B + (long)bz * strB + (long)(bn + lrow) * K);
        asp = smb + (uint32_t)((isA ? 0 : AWB) + lrow * SAB);
    } else {
        agp = A + (long)bz * strA + (long)(bm + tid) * K;
        asp = smb + (uint32_t)(tid * SAB);
        bgp = B + (long)bz * strB + (long)(bn + (tid >> 1)) * K + (tid & 1) * 8;
        bsp = smb + (uint32_t)(AWB + (tid >> 1) * SAB + (tid & 1) * 16);
    }

    auto loadt = [&](int kt, int st) {
        const uint32_t so = (uint32_t)(st * STAGEB);
        const __half* gp = agp + kt * 16;
        cpa16(asp + so,      gp);
        cpa16(asp + so + 16, gp + 8);
        if constexpr (NB == 64) cpa16(bsp + so, bgp + kt * 16);
    };

    const uint32_t aAddr = smb +
        (uint32_t)((wm * 32 + (lane & 7) + 8 * ((lane >> 3) & 1)) * SAB
                   + (lane >> 4) * 16);
    const uint32_t bAddr = smb +
        (uint32_t)(AWB + (wn * 64 + (lane & 7) + 8 * (lane >> 4)) * SAB
                   + ((lane >> 3) & 1) * 16);

    float acc[2][8][4];
    #pragma unroll
    for (int i = 0; i < 2; i++)
        #pragma unroll
        for (int j = 0; j < 8; j++)
            #pragma unroll
            for (int q = 0; q < 4; q++) acc[i][j][q] = 0.f;

    auto compute = [&](int st) {
        const uint32_t stoff = (uint32_t)(st * STAGEB);
        uint32_t af[2][4];
        ldsm4(af[0], aAddr + stoff);
        ldsm4(af[1], aAddr + stoff + 16 * SAB);
        uint32_t bf[4][4];
        #pragma unroll
        for (int p = 0; p < 4; p++)
            ldsm4(bf[p], bAddr + stoff + (uint32_t)(p * 16 * SAB));
        #pragma unroll
        for (int ni = 0; ni < 8; ni++) {
            const uint32_t* bb = &bf[ni >> 1][(ni & 1) * 2];
            mma16(acc[0][ni], af[0], bb);
            mma16(acc[1][ni], af[1], bb);
        }
    };

    const int nk = K / 16;
    loadt(0, 0); CPA_COMMIT();
    loadt(1, 1); CPA_COMMIT();
    loadt(2, 2); CPA_COMMIT();
    for (int kt = 0; kt < nk; kt++) {
        const int s = kt & 3;
        CPA_WAIT2();
        __syncthreads();
        if (kt + 3 < nk) loadt(kt + 3, (kt + 3) & 3);
        CPA_COMMIT();
        compute(s);
    }

    const int g = lane >> 2, t2 = (lane & 3) * 2;
    #pragma unroll
    for (int mi = 0; mi < 2; mi++) {
        #pragma unroll
        for (int half = 0; half < 2; half++) {
            const int m = bm + wm * 32 + mi * 16 + half * 8 + g;
            float addM = 0.f, sc = 1.f, be = 0.f, gwv = 0.f;
            if constexpr (EPI >= 1) { addM = bM[m]; sc = bng[m] * BN_INV; be = bnb[m]; }
            const long obase = (long)bz * strC + (long)m * ldc;
            const float* rrow = nullptr;
            float* o2row = nullptr;
            if constexpr (EPI >= 1) rrow = resid + (long)bz * sR + (long)m * ldc;
            if constexpr (EPI == 2) {
                o2row = out2 + (long)bz * strC + (long)m * ldc;
                gwv = cw[(long)bz * (gridDim.y * 128) + m];
            }
            #pragma unroll
            for (int ni = 0; ni < 8; ni++) {
                const int n = bn + wn * 64 + ni * 8 + t2;
                const float c0 = acc[mi][ni][half * 2 + 0];
                const float c1 = acc[mi][ni][half * 2 + 1];
                if constexpr (EPI == 0) {
                    *(__half2*)((__half*)Co + obase + n) =
                        __floats2half2_rn(alpha * c0, alpha * c1);
                } else {
                    float2 rv = *(const float2*)&rrow[n];
                    float2 o;
                    o.x = sc * (c0 + addM) + be + rv.x;
                    o.y = sc * (c1 + addM) + be + rv.y;
                    *(float2*)((float*)Co + obase + n) = o;
                    if constexpr (EPI == 2) {
                        float2 o2 = { o.x * gwv, o.y * gwv };
                        *(float2*)&o2row[n] = o2;
                    }
                }
            }
        }
    }
}

// ---------------------------------------------------------------------------
// Descriptor-batched fp16 GEMM (EPI0, NB=128): several independent GEMMs in
// one launch. Each CTA locates its segment, decodes (bx, by, bz), then runs
// the identical pipeline. bmode: 0 none, 1 row bias bM[m], 2 col bias bN[n].
// ---------------------------------------------------------------------------
struct GDesc {
    const __half *A, *B;
    __half *Co;
    const float *bM, *bN;
    long strA, strB, strC;
    int K, ldc, bmode, nx, ny, ctaEnd;
    float alpha;
};
struct GDesc4 { GDesc d[4]; int n; };

__global__ void __launch_bounds__(256, 2)
mgemm(GDesc4 P)
{
    constexpr int AWB    = 128 * SAB;
    constexpr int STAGEB = 256 * SAB;

    extern __shared__ uint32_t sm[];
    const uint32_t smb = smem_u32(sm);

    // segment lookup
    int s = 0;
    #pragma unroll
    for (int i = 0; i < 3; i++)
        if (i < P.n - 1 && (int)blockIdx.x >= P.d[i].ctaEnd && s == i) s = i + 1;
    const GDesc D = P.d[s];
    const int base = (s == 0) ? 0 : P.d[s - 1].ctaEnd;
    const int local = (int)blockIdx.x - base;
    const int bx = local % D.nx;
    const int tq = local / D.nx;
    const int by = tq % D.ny;
    const int bz = tq / D.ny;

    const int tid = threadIdx.x, lane = tid & 31, wid = tid >> 5;
    const int wm = wid & 3, wn = wid >> 2;
    const int bm = by * 128, bn = bx * 128;
    const int K = D.K;

    const int lrow = tid & 127;
    const bool isA = tid < 128;
    const __half* agp = (isA
        ? D.A + (long)bz * D.strA + (long)(bm + lrow) * K
        : D.B + (long)bz * D.strB + (long)(bn + lrow) * K);
    const uint32_t asp = smb + (uint32_t)((isA ? 0 : AWB) + lrow * SAB);

    auto loadt = [&](int kt, int st) {
        const uint32_t so = (uint32_t)(st * STAGEB);
        const __half* gp = agp + kt * 16;
        cpa16(asp + so,      gp);
        cpa16(asp + so + 16, gp + 8);
    };

    const uint32_t aAddr = smb +
        (uint32_t)((wm * 32 + (lane & 7) + 8 * ((lane >> 3) & 1)) * SAB
                   + (lane >> 4) * 16);
    const uint32_t bAddr = smb +
        (uint32_t)(AWB + (wn * 64 + (lane & 7) + 8 * (lane >> 4)) * SAB
                   + ((lane >> 3) & 1) * 16);

    float acc[2][8][4];
    #pragma unroll
    for (int i = 0; i < 2; i++)
        #pragma unroll
        for (int j = 0; j < 8; j++)
            #pragma unroll
            for (int q = 0; q < 4; q++) acc[i][j][q] = 0.f;

    auto compute = [&](int st) {
        const uint32_t stoff = (uint32_t)(st * STAGEB);
        uint32_t af[2][4];
        ldsm4(af[0], aAddr + stoff);
        ldsm4(af[1], aAddr + stoff + 16 * SAB);
        uint32_t bf[4][4];
        #pragma unroll
        for (int p = 0; p < 4; p++)
            ldsm4(bf[p], bAddr + stoff + (uint32_t)(p * 16 * SAB));
        #pragma unroll
        for (int ni = 0; ni < 8; ni++) {
            const uint32_t* bb = &bf[ni >> 1][(ni & 1) * 2];
            mma16(acc[0][ni], af[0], bb);
            mma16(acc[1][ni], af[1], bb);
        }
    };

    const int nk = K / 16;
    loadt(0, 0); CPA_COMMIT();
    loadt(1, 1); CPA_COMMIT();
    loadt(2, 2); CPA_COMMIT();
    for (int kt = 0; kt < nk; kt++) {
        const int st = kt & 3;
        CPA_WAIT2();
        __syncthreads();
        if (kt + 3 < nk) loadt(kt + 3, (kt + 3) & 3);
        CPA_COMMIT();
        compute(st);
    }

    const int g = lane >> 2, t2 = (lane & 3) * 2;
    #pragma unroll
    for (int mi = 0; mi < 2; mi++) {
        #pragma unroll
        for (int half = 0; half < 2; half++) {
            const int m = bm + wm * 32 + mi * 16 + half * 8 + g;
            const float addM = (D.bmode == 1) ? D.bM[m] : 0.f;
            __half* crow = D.Co + (long)bz * D.strC + (long)m * D.ldc;
            #pragma unroll
            for (int ni = 0; ni < 8; ni++) {
                const int n = bn + wn * 64 + ni * 8 + t2;
                float ox = D.alpha * acc[mi][ni][half * 2 + 0] + addM;
                float oy = D.alpha * acc[mi][ni][half * 2 + 1] + addM;
                if (D.bmode == 2) { ox += D.bN[n]; oy += D.bN[n + 1]; }
                *(__half2*)(crow + n) = __floats2half2_rn(ox, oy);
            }
        }
    }
}

// ---------------------------------------------------------------------------
// Merged weight conversion fp32 -> fp16 (5 matrices)
// ---------------------------------------------------------------------------
__global__ void round5_k(const float* s0, const float* s1, const float* s2,
                         const float* s3, const float* s4,
                         __half* d0, __half* d1, __half* d2, __half* d3, __half* d4,
                         int n4)
{
    const float* s; __half* d;
    switch (blockIdx.y) {
        case 0:  s = s0; d = d0; break;
        case 1:  s = s1; d = d1; break;
        case 2:  s = s2; d = d2; break;
        case 3:  s = s3; d = d3; break;
        default: s = s4; d = d4; break;
    }
    const int i = blockIdx.x * blockDim.x + threadIdx.x;
    if (i >= n4) return;
    float4 v = ((const float4*)s)[i];
    ((__half2*)d)[2 * i + 0] = __floats2half2_rn(v.x, v.y);
    ((__half2*)d)[2 * i + 1] = __floats2half2_rn(v.z, v.w);
}

// ---------------------------------------------------------------------------
// Transpose fp32 -> fp16
// ---------------------------------------------------------------------------
__global__ void transpose_f2h_k(const float* __restrict__ src, __half* __restrict__ dst,
                                int rows, int cols)
{
    __shared__ float t[32][33];
    const long bo = (long)blockIdx.z * rows * cols;
    const int c0 = blockIdx.x * 32, r0 = blockIdx.y * 32;
    const int tx = threadIdx.x, ty = threadIdx.y;
    #pragma unroll
    for (int i = 0; i < 32; i += 8)
        t[ty + i][tx] = src[bo + (long)(r0 + ty + i) * cols + c0 + tx];
    __syncthreads();
    #pragma unroll
    for (int i = 0; i < 32; i += 8)
        dst[bo + (long)(c0 + ty + i) * rows + r0 + tx] = __float2half_rn(t[tx][ty + i]);
}

// ---------------------------------------------------------------------------
// Transpose half -> half (fT = transpose(f))
// ---------------------------------------------------------------------------
__global__ void transpose_h_k(const __half* __restrict__ src, __half* __restrict__ dst,
                              int rows, int cols)
{
    __shared__ __half t[32][33];
    const long bo = (long)blockIdx.z * rows * cols;
    const int c0 = blockIdx.x * 32, r0 = blockIdx.y * 32;
    const int tx = threadIdx.x, ty = threadIdx.y;
    #pragma unroll
    for (int i = 0; i < 32; i += 8)
        t[ty + i][tx] = src[bo + (long)(r0 + ty + i) * cols + c0 + tx];
    __syncthreads();
    #pragma unroll
    for (int i = 0; i < 32; i += 8)
        dst[bo + (long)(c0 + ty + i) * rows + r0 + tx] = t[tx][ty + i];
}

// ---------------------------------------------------------------------------
// Avg+Max pooling: one warp per (b,c)
// ---------------------------------------------------------------------------
__global__ void pool_k(const float* __restrict__ na, float* __restrict__ pooled)
{
    const int gw = (int)((blockIdx.x * (long)blockDim.x + threadIdx.x) >> 5);
    const int lane = threadIdx.x & 31;
    if (gw >= Bc * C) return;
    const float* p = na + (long)gw * Na;
    float s = 0.f, m = -3.4e38f;
    for (int i = lane; i < Na; i += 32) { float v = p[i]; s += v; m = fmaxf(m, v); }
    #pragma unroll
    for (int o = 16; o; o >>= 1) {
        s += __shfl_xor_sync(0xffffffffu, s, o);
        m = fmaxf(m, __shfl_xor_sync(0xffffffffu, m, o));
    }
    if (lane == 0) {
        const int b = gw / C, c = gw % C;
        pooled[(long)b * 2 * C + c]     = s * (1.f / Na);
        pooled[(long)b * 2 * C + C + c] = m;
    }
}

// ---------------------------------------------------------------------------
// Channel gate MLP + sigmoid
// ---------------------------------------------------------------------------
__global__ void gate_k(const float* __restrict__ pooled,
                       const float* __restrict__ w1, const float* __restrict__ b1,
                       const float* __restrict__ w2, const float* __restrict__ b2,
                       float* __restrict__ cw)
{
    __shared__ float sv[2 * C];
    __shared__ float h[2][R];
    __shared__ float hs[R];
    const int b = blockIdx.x, tid = threadIdx.x;
    for (int i = tid; i < 2 * C; i += blockDim.x)
        sv[i] = pooled[(long)b * 2 * C + i];
    __syncthreads();
    if (tid < 2 * R) {
        const int which = tid / R, r = tid % R;
        const float* v = sv + which * C;
        const float* wr = w1 + r * C;
        float acc = b1[r];
        for (int c = 0; c < C; c++) acc += wr[c] * v[c];
        h[which][r] = fmaxf(acc, 0.f);
    }
    __syncthreads();
    if (tid < R) hs[tid] = h[0][tid] + h[1][tid];
    __syncthreads();
    for (int c = tid; c < C; c += blockDim.x) {
        const float* wc = w2 + c * R;
        float acc = 2.f * b2[c];
        #pragma unroll 8
        for (int r = 0; r < R; r++) acc += wc[r] * hs[r];
        cw[(long)b * C + c] = 1.f / (1.f + expf(-acc));
    }
}

// ---------------------------------------------------------------------------
// Channel scaling (act_aim)
// ---------------------------------------------------------------------------
__global__ void scale_k(const float* __restrict__ src, const float* __restrict__ cw,
                        float* __restrict__ dst, int q_div, long total4)
{
    const long i = blockIdx.x * (long)blockDim.x + threadIdx.x;
    if (i >= total4) return;
    const float w = cw[i / q_div];
    float4 v = ((const float4*)src)[i];
    v.x *= w; v.y *= w; v.z *= w; v.w *= w;
    ((float4*)dst)[i] = v;
}

// ---------------------------------------------------------------------------
// Launch
// ---------------------------------------------------------------------------
extern "C" void kernel_launch(void* const* d_in, const int* in_sizes, int n_in,
                              void* d_out, int out_size)
{
    (void)in_sizes; (void)n_in; (void)out_size;
    const float* detect = (const float*)d_in[0];
    const float* aim    = (const float*)d_in[1];
    const float* g_w    = (const float*)d_in[2];
    const float* g_b    = (const float*)d_in[3];
    const float* th_w   = (const float*)d_in[4];
    const float* th_b   = (const float*)d_in[5];
    const float* ph_w   = (const float*)d_in[6];
    const float* ph_b   = (const float*)d_in[7];
    const float* W_w    = (const float*)d_in[8];
    const float* W_b    = (const float*)d_in[9];
    const float* W_bn_g = (const float*)d_in[10];
    const float* W_bn_b = (const float*)d_in[11];
    const float* Q_w    = (const float*)d_in[12];
    const float* Q_b    = (const float*)d_in[13];
    const float* Q_bn_g = (const float*)d_in[14];
    const float* Q_bn_b = (const float*)d_in[15];
    const float* m1_w   = (const float*)d_in[16];
    const float* m1_b   = (const float*)d_in[17];
    const float* m2_w   = (const float*)d_in[18];
    const float* m2_b   = (const float*)d_in[19];
    float* out = (float*)d_out;

    __half *detT, *aimT, *dx, *phx, *ax, *thx, *fm, *fT, *nap, *ndp;
    __half *gwr, *thwr, *phwr, *Wwr, *Qwr;
    float *nonaim, *pooled;
    cudaGetSymbolAddress((void**)&detT,   g_detT);
    cudaGetSymbolAddress((void**)&aimT,   g_aimT);
    cudaGetSymbolAddress((void**)&dx,     g_dx);
    cudaGetSymbolAddress((void**)&phx,    g_phx);
    cudaGetSymbolAddress((void**)&ax,     g_ax);
    cudaGetSymbolAddress((void**)&thx,    g_thx);
    cudaGetSymbolAddress((void**)&fm,     g_fm);
    cudaGetSymbolAddress((void**)&fT,     g_fT);
    cudaGetSymbolAddress((void**)&nap,    g_nap);
    cudaGetSymbolAddress((void**)&ndp,    g_ndp);
    cudaGetSymbolAddress((void**)&nonaim, g_nonaim);
    cudaGetSymbolAddress((void**)&pooled, g_pooled);
    cudaGetSymbolAddress((void**)&gwr,    g_gwr);
    cudaGetSymbolAddress((void**)&thwr,   g_thwr);
    cudaGetSymbolAddress((void**)&phwr,   g_phwr);
    cudaGetSymbolAddress((void**)&Wwr,    g_Wwr);
    cudaGetSymbolAddress((void**)&Qwr,    g_Qwr);

    const long offNonDet = 0;
    const long offActDet = (long)Bc * C * Nd;
    const long offActAim = 2 * offActDet;
    const long offCw     = offActAim + (long)Bc * C * Na;

    cudaFuncSetAttribute(mgemm,        cudaFuncAttributeMaxDynamicSharedMemorySize, GS128);
    cudaFuncSetAttribute(tgemm<0,128>, cudaFuncAttributeMaxDynamicSharedMemorySize, GS128);
    cudaFuncSetAttribute(tgemm<2,128>, cudaFuncAttributeMaxDynamicSharedMemorySize, GS128);
    cudaFuncSetAttribute(tgemm<1,64>,  cudaFuncAttributeMaxDynamicSharedMemorySize, GS64);

    const int n4 = (Ci * C) / 4;

    // prologue
    transpose_f2h_k<<<dim3(Nd / 32, C / 32, Bc), dim3(32, 8)>>>(detect, detT, C, Nd);
    transpose_f2h_k<<<dim3(Na / 32, C / 32, Bc), dim3(32, 8)>>>(aim,    aimT, C, Na);
    round5_k<<<dim3((n4 + 255) / 256, 5), 256>>>(
        g_w, th_w, ph_w, W_w, Q_w, gwr, thwr, phwr, Wwr, Qwr, n4);

    // MERGE1: G1 + G2 + G3 + G4 (all independent)
    {
        GDesc4 P; P.n = 4;
        int off = 0;
        // G1: dx[Ci,Nd] = gwr * detT^T + g_b[m]
        off += 18 * 4 * Bc;
        P.d[0] = { gwr, detT, dx, g_b, nullptr, 0, (long)Nd*C, (long)Ci*Nd,
                   C, Nd, 1, 18, 4, off, 1.f };
        // G2: phx[Nd,Ci] = detT * phwr^T + ph_b[n]
        off += 4 * 18 * Bc;
        P.d[1] = { detT, phwr, phx, nullptr, ph_b, (long)Nd*C, 0, (long)Nd*Ci,
                   C, Ci, 2, 4, 18, off, 1.f };
        // G3: ax[Ci,Na] = gwr * aimT^T + g_b[m]
        off += 2 * 4 * Bc;
        P.d[2] = { gwr, aimT, ax, g_b, nullptr, 0, (long)Na*C, (long)Ci*Na,
                   C, Na, 1, 2, 4, off, 1.f };
        // G4: thx[Na,Ci] = aimT * thwr^T + th_b[n]
        off += 4 * 2 * Bc;
        P.d[3] = { aimT, thwr, thx, nullptr, th_b, (long)Na*C, 0, (long)Na*Ci,
                   C, Ci, 2, 4, 2, off, 1.f };
        mgemm<<<off, 256, GS128>>>(P);
    }

    // G5: f[Na,Nd] = theta * phi^T
    tgemm<0,128><<<dim3(Nd/128, Na/128, Bc), 256, GS128>>>(
        thx, phx, fm, Ci, Nd, (long)Na*Ci, (long)Nd*Ci, (long)Na*Nd, 1.f,
        nullptr, nullptr, nullptr, nullptr, 0, nullptr, nullptr);
    // T5b: fT = transpose(f)
    transpose_h_k<<<dim3(Nd / 32, Na / 32, Bc), dim3(32, 8)>>>(fm, fT, Na, Nd);

    // MERGE2: G7 + G6 (independent)
    {
        GDesc4 P; P.n = 2;
        int off = 0;
        // G7: ndp[Nd,Ci] = (1/Na) fT * ax^T
        off += 4 * 18 * Bc;
        P.d[0] = { fT, ax, ndp, nullptr, nullptr, (long)Nd*Na, (long)Ci*Na, (long)Nd*Ci,
                   Na, Ci, 0, 4, 18, off, 1.f / Na };
        // G6: nap[Na,Ci] = (1/Nd) f * dx^T
        off += 4 * 2 * Bc;
        P.d[1] = { fm, dx, nap, nullptr, nullptr, (long)Na*Nd, (long)Ci*Nd, (long)Na*Ci,
                   Nd, Ci, 0, 4, 2, off, 1.f / Nd };
        P.d[2] = P.d[1]; P.d[3] = P.d[1];   // unused
        mgemm<<<off, 256, GS128>>>(P);
    }

    // G8: non_aim[C,Na] = bn(Wwr * nap^T + W_b) + aim   (fp32 out)
    tgemm<1,64><<<dim3(Na/64, C/128, Bc), 128, GS64>>>(
        Wwr, nap, nonaim, Ci, Na, 0, (long)Na*Ci, (long)C*Na, 1.f,
        W_b, W_bn_g, W_bn_b, aim, (long)C*Na, nullptr, nullptr);
    // pool + gate
    pool_k<<<(Bc * C) / 8, 256>>>(nonaim, pooled);
    gate_k<<<Bc, 256>>>(pooled, m1_w, m1_b, m2_w, m2_b, out + offCw);
    // G9: non_det + act_det fused
    tgemm<2,128><<<dim3(Nd/128, C/128, Bc), 256, GS128>>>(
        Qwr, ndp, out + offNonDet, Ci, Nd, 0, (long)Nd*Ci, (long)C*Nd, 1.f,
        Q_b, Q_bn_g, Q_bn_b, detect, (long)C*Nd,
        out + offCw, out + offActDet);
    // act_aim = non_aim * cw
    const long t4a = (long)Bc * C * Na / 4;
    scale_k<<<(unsigned)((t4a + 255) / 256), 256>>>(
        nonaim, out + offCw, out + offActAim, Na / 4, t4a);
}

// round 17
// speedup vs baseline: 1.0665x; 1.0665x over previous
#include <cuda_runtime.h>
#include <cuda_fp16.h>
#include <cstdint>
#include <math.h>

// ---------------------------------------------------------------------------
// Problem constants
// ---------------------------------------------------------------------------
constexpr int Bc = 8;
constexpr int C  = 1024;
constexpr int Ci = 512;
constexpr int Nd = 48 * 48;          // 2304
constexpr int Na = 16 * 16;          // 256
constexpr int R  = 64;               // C / 16
constexpr float BN_INV = 0.9999950000374997f;  // 1/sqrt(1+1e-5)

// ---------------------------------------------------------------------------
// Device scratch (static); GEMM operands fp16 (same mantissa as tf32)
// ---------------------------------------------------------------------------
__device__ __half g_detT  [Bc * Nd * C];
__device__ __half g_aimT  [Bc * Na * C];
__device__ __half g_dx    [Bc * Ci * Nd];
__device__ __half g_phx   [Bc * Nd * Ci];
__device__ __half g_ax    [Bc * Ci * Na];
__device__ __half g_thx   [Bc * Na * Ci];
__device__ __half g_fm    [Bc * Na * Nd];
__device__ __half g_fT    [Bc * Nd * Na];
__device__ __half g_nap   [Bc * Na * Ci];
__device__ __half g_ndp   [Bc * Nd * Ci];
__device__ float  g_nonaim[Bc * C  * Na];
__device__ float  g_pooled[Bc * 2  * C];
__device__ __half g_gwr [Ci * C];
__device__ __half g_thwr[Ci * C];
__device__ __half g_phwr[Ci * C];
__device__ __half g_Wwr [C * Ci];
__device__ __half g_Qwr [C * Ci];

// ---------------------------------------------------------------------------
// helpers
// ---------------------------------------------------------------------------
__device__ __forceinline__ uint32_t smem_u32(const void* p) {
    uint32_t a;
    asm("{ .reg .u64 t; cvta.to.shared.u64 t, %1; cvt.u32.u64 %0, t; }" : "=r"(a) : "l"(p));
    return a;
}
__device__ __forceinline__ void mma16(float* d, const uint32_t* a, const uint32_t* b) {
    asm volatile(
        "mma.sync.aligned.m16n8k16.row.col.f32.f16.f16.f32 "
        "{%0,%1,%2,%3}, {%4,%5,%6,%7}, {%8,%9}, {%0,%1,%2,%3};"
        : "+f"(d[0]), "+f"(d[1]), "+f"(d[2]), "+f"(d[3])
        : "r"(a[0]), "r"(a[1]), "r"(a[2]), "r"(a[3]), "r"(b[0]), "r"(b[1]));
}
__device__ __forceinline__ void ldsm4(uint32_t* r, uint32_t a) {
    asm volatile("ldmatrix.sync.aligned.m8n8.x4.shared.b16 {%0,%1,%2,%3}, [%4];"
        : "=r"(r[0]), "=r"(r[1]), "=r"(r[2]), "=r"(r[3]) : "r"(a));
}
__device__ __forceinline__ void cpa16(uint32_t s, const void* g) {
    asm volatile("cp.async.cg.shared.global [%0], [%1], 16;" :: "r"(s), "l"(g));
}
#define CPA_COMMIT() asm volatile("cp.async.commit_group;" ::: "memory")
#define CPA_WAIT2()  asm volatile("cp.async.wait_group 2;" ::: "memory")

constexpr int SAB  = 48;               // smem row stride bytes (32 + 16)
constexpr int NSTG = 4;
constexpr int GS128 = NSTG * (128 + 128) * SAB;   // 49152 B
constexpr int GS64  = NSTG * (128 + 64)  * SAB;   // 36864 B

// ---------------------------------------------------------------------------
// Templated fp16 GEMM (R14-committed config).
//   D[M,N] = alpha*A[M,K]*B[N,K]^T; block 128xNB; warp tile 32x64; BK=16;
//   4-stage cp.async; ldmatrix.x4 fragments.
//   EPI 0: half out = alpha*acc
//   EPI 1: float out = bng[m]*BN_INV*(acc+bM[m]) + bnb[m] + resid
//   EPI 2: EPI1 + out2 = v * cw[bz*M + m]
// ---------------------------------------------------------------------------
template<int EPI, int NB>
__global__ void __launch_bounds__(NB * 2, (NB == 128) ? 2 : 3)
tgemm(const __half* __restrict__ A, const __half* __restrict__ B,
      void* __restrict__ Co,
      int K, int ldc, long strA, long strB, long strC, float alpha,
      const float* __restrict__ bM,
      const float* __restrict__ bng, const float* __restrict__ bnb,
      const float* __restrict__ resid, long sR,
      const float* __restrict__ cw, float* __restrict__ out2)
{
    constexpr int AWB    = 128 * SAB;
    constexpr int STAGEB = (128 + NB) * SAB;

    extern __shared__ uint32_t sm[];
    const uint32_t smb = smem_u32(sm);

    const int tid = threadIdx.x, lane = tid & 31, wid = tid >> 5;
    const int wm = wid & 3, wn = wid >> 2;
    const int bz = blockIdx.z;
    const int bm = blockIdx.y * 128, bn = blockIdx.x * NB;

    const __half* agp;  uint32_t asp;
    const __half* bgp = nullptr;  uint32_t bsp = 0;
    if constexpr (NB == 128) {
        const int lrow = tid & 127;
        const bool isA = tid < 128;
        agp = (isA ? A + (long)bz * strA + (long)(bm + lrow) * K
                   : B + (long)bz * strB + (long)(bn + lrow) * K);
        asp = smb + (uint32_t)((isA ? 0 : AWB) + lrow * SAB);
    } else {
        agp = A + (long)bz * strA + (long)(bm + tid) * K;
        asp = smb + (uint32_t)(tid * SAB);
        bgp = B + (long)bz * strB + (long)(bn + (tid >> 1)) * K + (tid & 1) * 8;
        bsp = smb + (uint32_t)(AWB + (tid >> 1) * SAB + (tid & 1) * 16);
    }

    auto loadt = [&](int kt, int st) {
        const uint32_t so = (uint32_t)(st * STAGEB);
        const __half* gp = agp + kt * 16;
        cpa16(asp + so,      gp);
        cpa16(asp + so + 16, gp + 8);
        if constexpr (NB == 64) cpa16(bsp + so, bgp + kt * 16);
    };

    const uint32_t aAddr = smb +
        (uint32_t)((wm * 32 + (lane & 7) + 8 * ((lane >> 3) & 1)) * SAB
                   + (lane >> 4) * 16);
    const uint32_t bAddr = smb +
        (uint32_t)(AWB + (wn * 64 + (lane & 7) + 8 * (lane >> 4)) * SAB
                   + ((lane >> 3) & 1) * 16);

    float acc[2][8][4];
    #pragma unroll
    for (int i = 0; i < 2; i++)
        #pragma unroll
        for (int j = 0; j < 8; j++)
            #pragma unroll
            for (int q = 0; q < 4; q++) acc[i][j][q] = 0.f;

    auto compute = [&](int st) {
        const uint32_t stoff = (uint32_t)(st * STAGEB);
        uint32_t af[2][4];
        ldsm4(af[0], aAddr + stoff);
        ldsm4(af[1], aAddr + stoff + 16 * SAB);
        uint32_t bf[4][4];
        #pragma unroll
        for (int p = 0; p < 4; p++)
            ldsm4(bf[p], bAddr + stoff + (uint32_t)(p * 16 * SAB));
        #pragma unroll
        for (int ni = 0; ni < 8; ni++) {
            const uint32_t* bb = &bf[ni >> 1][(ni & 1) * 2];
            mma16(acc[0][ni], af[0], bb);
            mma16(acc[1][ni], af[1], bb);
        }
    };

    const int nk = K / 16;
    loadt(0, 0); CPA_COMMIT();
    loadt(1, 1); CPA_COMMIT();
    loadt(2, 2); CPA_COMMIT();
    for (int kt = 0; kt < nk; kt++) {
        const int s = kt & 3;
        CPA_WAIT2();
        __syncthreads();
        if (kt + 3 < nk) loadt(kt + 3, (kt + 3) & 3);
        CPA_COMMIT();
        compute(s);
    }

    const int g = lane >> 2, t2 = (lane & 3) * 2;
    #pragma unroll
    for (int mi = 0; mi < 2; mi++) {
        #pragma unroll
        for (int half = 0; half < 2; half++) {
            const int m = bm + wm * 32 + mi * 16 + half * 8 + g;
            float addM = 0.f, sc = 1.f, be = 0.f, gwv = 0.f;
            if constexpr (EPI >= 1) { addM = bM[m]; sc = bng[m] * BN_INV; be = bnb[m]; }
            const long obase = (long)bz * strC + (long)m * ldc;
            const float* rrow = nullptr;
            float* o2row = nullptr;
            if constexpr (EPI >= 1) rrow = resid + (long)bz * sR + (long)m * ldc;
            if constexpr (EPI == 2) {
                o2row = out2 + (long)bz * strC + (long)m * ldc;
                gwv = cw[(long)bz * (gridDim.y * 128) + m];
            }
            #pragma unroll
            for (int ni = 0; ni < 8; ni++) {
                const int n = bn + wn * 64 + ni * 8 + t2;
                const float c0 = acc[mi][ni][half * 2 + 0];
                const float c1 = acc[mi][ni][half * 2 + 1];
                if constexpr (EPI == 0) {
                    *(__half2*)((__half*)Co + obase + n) =
                        __floats2half2_rn(alpha * c0, alpha * c1);
                } else {
                    float2 rv = *(const float2*)&rrow[n];
                    float2 o;
                    o.x = sc * (c0 + addM) + be + rv.x;
                    o.y = sc * (c1 + addM) + be + rv.y;
                    *(float2*)((float*)Co + obase + n) = o;
                    if constexpr (EPI == 2) {
                        float2 o2 = { o.x * gwv, o.y * gwv };
                        *(float2*)&o2row[n] = o2;
                    }
                }
            }
        }
    }
}

// ---------------------------------------------------------------------------
// Descriptor-batched fp16 GEMM (EPI0, NB=128) — used ONLY for MERGE1
// (G1+G2+G3+G4: uniform K=1024, no long-K tail; measured -13us in R15).
// bmode: 0 none, 1 row bias bM[m], 2 col bias bN[n].
// ---------------------------------------------------------------------------
struct GDesc {
    const __half *A, *B;
    __half *Co;
    const float *bM, *bN;
    long strA, strB, strC;
    int K, ldc, bmode, nx, ny, ctaEnd;
    float alpha;
};
struct GDesc4 { GDesc d[4]; int n; };

__global__ void __launch_bounds__(256, 2)
mgemm(GDesc4 P)
{
    constexpr int AWB    = 128 * SAB;
    constexpr int STAGEB = 256 * SAB;

    extern __shared__ uint32_t sm[];
    const uint32_t smb = smem_u32(sm);

    int s = 0;
    #pragma unroll
    for (int i = 0; i < 3; i++)
        if (i < P.n - 1 && (int)blockIdx.x >= P.d[i].ctaEnd && s == i) s = i + 1;
    const GDesc D = P.d[s];
    const int base = (s == 0) ? 0 : P.d[s - 1].ctaEnd;
    const int local = (int)blockIdx.x - base;
    const int bx = local % D.nx;
    const int tq = local / D.nx;
    const int by = tq % D.ny;
    const int bz = tq / D.ny;

    const int tid = threadIdx.x, lane = tid & 31, wid = tid >> 5;
    const int wm = wid & 3, wn = wid >> 2;
    const int bm = by * 128, bn = bx * 128;
    const int K = D.K;

    const int lrow = tid & 127;
    const bool isA = tid < 128;
    const __half* agp = (isA
        ? D.A + (long)bz * D.strA + (long)(bm + lrow) * K
        : D.B + (long)bz * D.strB + (long)(bn + lrow) * K);
    const uint32_t asp = smb + (uint32_t)((isA ? 0 : AWB) + lrow * SAB);

    auto loadt = [&](int kt, int st) {
        const uint32_t so = (uint32_t)(st * STAGEB);
        const __half* gp = agp + kt * 16;
        cpa16(asp + so,      gp);
        cpa16(asp + so + 16, gp + 8);
    };

    const uint32_t aAddr = smb +
        (uint32_t)((wm * 32 + (lane & 7) + 8 * ((lane >> 3) & 1)) * SAB
                   + (lane >> 4) * 16);
    const uint32_t bAddr = smb +
        (uint32_t)(AWB + (wn * 64 + (lane & 7) + 8 * (lane >> 4)) * SAB
                   + ((lane >> 3) & 1) * 16);

    float acc[2][8][4];
    #pragma unroll
    for (int i = 0; i < 2; i++)
        #pragma unroll
        for (int j = 0; j < 8; j++)
            #pragma unroll
            for (int q = 0; q < 4; q++) acc[i][j][q] = 0.f;

    auto compute = [&](int st) {
        const uint32_t stoff = (uint32_t)(st * STAGEB);
        uint32_t af[2][4];
        ldsm4(af[0], aAddr + stoff);
        ldsm4(af[1], aAddr + stoff + 16 * SAB);
        uint32_t bf[4][4];
        #pragma unroll
        for (int p = 0; p < 4; p++)
            ldsm4(bf[p], bAddr + stoff + (uint32_t)(p * 16 * SAB));
        #pragma unroll
        for (int ni = 0; ni < 8; ni++) {
            const uint32_t* bb = &bf[ni >> 1][(ni & 1) * 2];
            mma16(acc[0][ni], af[0], bb);
            mma16(acc[1][ni], af[1], bb);
        }
    };

    const int nk = K / 16;
    loadt(0, 0); CPA_COMMIT();
    loadt(1, 1); CPA_COMMIT();
    loadt(2, 2); CPA_COMMIT();
    for (int kt = 0; kt < nk; kt++) {
        const int st = kt & 3;
        CPA_WAIT2();
        __syncthreads();
        if (kt + 3 < nk) loadt(kt + 3, (kt + 3) & 3);
        CPA_COMMIT();
        compute(st);
    }

    const int g = lane >> 2, t2 = (lane & 3) * 2;
    #pragma unroll
    for (int mi = 0; mi < 2; mi++) {
        #pragma unroll
        for (int half = 0; half < 2; half++) {
            const int m = bm + wm * 32 + mi * 16 + half * 8 + g;
            const float addM = (D.bmode == 1) ? D.bM[m] : 0.f;
            __half* crow = D.Co + (long)bz * D.strC + (long)m * D.ldc;
            #pragma unroll
            for (int ni = 0; ni < 8; ni++) {
                const int n = bn + wn * 64 + ni * 8 + t2;
                float ox = D.alpha * acc[mi][ni][half * 2 + 0] + addM;
                float oy = D.alpha * acc[mi][ni][half * 2 + 1] + addM;
                if (D.bmode == 2) { ox += D.bN[n]; oy += D.bN[n + 1]; }
                *(__half2*)(crow + n) = __floats2half2_rn(ox, oy);
            }
        }
    }
}

// ---------------------------------------------------------------------------
// Merged weight conversion fp32 -> fp16 (5 matrices)
// ---------------------------------------------------------------------------
__global__ void round5_k(const float* s0, const float* s1, const float* s2,
                         const float* s3, const float* s4,
                         __half* d0, __half* d1, __half* d2, __half* d3, __half* d4,
                         int n4)
{
    const float* s; __half* d;
    switch (blockIdx.y) {
        case 0:  s = s0; d = d0; break;
        case 1:  s = s1; d = d1; break;
        case 2:  s = s2; d = d2; break;
        case 3:  s = s3; d = d3; break;
        default: s = s4; d = d4; break;
    }
    const int i = blockIdx.x * blockDim.x + threadIdx.x;
    if (i >= n4) return;
    float4 v = ((const float4*)s)[i];
    ((__half2*)d)[2 * i + 0] = __floats2half2_rn(v.x, v.y);
    ((__half2*)d)[2 * i + 1] = __floats2half2_rn(v.z, v.w);
}

// ---------------------------------------------------------------------------
// Transpose fp32 -> fp16
// ---------------------------------------------------------------------------
__global__ void transpose_f2h_k(const float* __restrict__ src, __half* __restrict__ dst,
                                int rows, int cols)
{
    __shared__ float t[32][33];
    const long bo = (long)blockIdx.z * rows * cols;
    const int c0 = blockIdx.x * 32, r0 = blockIdx.y * 32;
    const int tx = threadIdx.x, ty = threadIdx.y;
    #pragma unroll
    for (int i = 0; i < 32; i += 8)
        t[ty + i][tx] = src[bo + (long)(r0 + ty + i) * cols + c0 + tx];
    __syncthreads();
    #pragma unroll
    for (int i = 0; i < 32; i += 8)
        dst[bo + (long)(c0 + ty + i) * rows + r0 + tx] = __float2half_rn(t[tx][ty + i]);
}

// ---------------------------------------------------------------------------
// Transpose half -> half (fT = transpose(f); bit-exact)
// ---------------------------------------------------------------------------
__global__ void transpose_h_k(const __half* __restrict__ src, __half* __restrict__ dst,
                              int rows, int cols)
{
    __shared__ __half t[32][33];
    const long bo = (long)blockIdx.z * rows * cols;
    const int c0 = blockIdx.x * 32, r0 = blockIdx.y * 32;
    const int tx = threadIdx.x, ty = threadIdx.y;
    #pragma unroll
    for (int i = 0; i < 32; i += 8)
        t[ty + i][tx] = src[bo + (long)(r0 + ty + i) * cols + c0 + tx];
    __syncthreads();
    #pragma unroll
    for (int i = 0; i < 32; i += 8)
        dst[bo + (long)(c0 + ty + i) * rows + r0 + tx] = t[tx][ty + i];
}

// ---------------------------------------------------------------------------
// Avg+Max pooling: one warp per (b,c)
// ---------------------------------------------------------------------------
__global__ void pool_k(const float* __restrict__ na, float* __restrict__ pooled)
{
    const int gw = (int)((blockIdx.x * (long)blockDim.x + threadIdx.x) >> 5);
    const int lane = threadIdx.x & 31;
    if (gw >= Bc * C) return;
    const float* p = na + (long)gw * Na;
    float s = 0.f, m = -3.4e38f;
    for (int i = lane; i < Na; i += 32) { float v = p[i]; s += v; m = fmaxf(m, v); }
    #pragma unroll
    for (int o = 16; o; o >>= 1) {
        s += __shfl_xor_sync(0xffffffffu, s, o);
        m = fmaxf(m, __shfl_xor_sync(0xffffffffu, m, o));
    }
    if (lane == 0) {
        const int b = gw / C, c = gw % C;
        pooled[(long)b * 2 * C + c]     = s * (1.f / Na);
        pooled[(long)b * 2 * C + C + c] = m;
    }
}

// ---------------------------------------------------------------------------
// Channel gate MLP + sigmoid
// ---------------------------------------------------------------------------
__global__ void gate_k(const float* __restrict__ pooled,
                       const float* __restrict__ w1, const float* __restrict__ b1,
                       const float* __restrict__ w2, const float* __restrict__ b2,
                       float* __restrict__ cw)
{
    __shared__ float sv[2 * C];
    __shared__ float h[2][R];
    __shared__ float hs[R];
    const int b = blockIdx.x, tid = threadIdx.x;
    for (int i = tid; i < 2 * C; i += blockDim.x)
        sv[i] = pooled[(long)b * 2 * C + i];
    __syncthreads();
    if (tid < 2 * R) {
        const int which = tid / R, r = tid % R;
        const float* v = sv + which * C;
        const float* wr = w1 + r * C;
        float acc = b1[r];
        for (int c = 0; c < C; c++) acc += wr[c] * v[c];
        h[which][r] = fmaxf(acc, 0.f);
    }
    __syncthreads();
    if (tid < R) hs[tid] = h[0][tid] + h[1][tid];
    __syncthreads();
    for (int c = tid; c < C; c += blockDim.x) {
        const float* wc = w2 + c * R;
        float acc = 2.f * b2[c];
        #pragma unroll 8
        for (int r = 0; r < R; r++) acc += wc[r] * hs[r];
        cw[(long)b * C + c] = 1.f / (1.f + expf(-acc));
    }
}

// ---------------------------------------------------------------------------
// Channel scaling (act_aim)
// ---------------------------------------------------------------------------
__global__ void scale_k(const float* __restrict__ src, const float* __restrict__ cw,
                        float* __restrict__ dst, int q_div, long total4)
{
    const long i = blockIdx.x * (long)blockDim.x + threadIdx.x;
    if (i >= total4) return;
    const float w = cw[i / q_div];
    float4 v = ((const float4*)src)[i];
    v.x *= w; v.y *= w; v.z *= w; v.w *= w;
    ((float4*)dst)[i] = v;
}

// ---------------------------------------------------------------------------
// Launch
// ---------------------------------------------------------------------------
extern "C" void kernel_launch(void* const* d_in, const int* in_sizes, int n_in,
                              void* d_out, int out_size)
{
    (void)in_sizes; (void)n_in; (void)out_size;
    const float* detect = (const float*)d_in[0];
    const float* aim    = (const float*)d_in[1];
    const float* g_w    = (const float*)d_in[2];
    const float* g_b    = (const float*)d_in[3];
    const float* th_w   = (const float*)d_in[4];
    const float* th_b   = (const float*)d_in[5];
    const float* ph_w   = (const float*)d_in[6];
    const float* ph_b   = (const float*)d_in[7];
    const float* W_w    = (const float*)d_in[8];
    const float* W_b    = (const float*)d_in[9];
    const float* W_bn_g = (const float*)d_in[10];
    const float* W_bn_b = (const float*)d_in[11];
    const float* Q_w    = (const float*)d_in[12];
    const float* Q_b    = (const float*)d_in[13];
    const float* Q_bn_g = (const float*)d_in[14];
    const float* Q_bn_b = (const float*)d_in[15];
    const float* m1_w   = (const float*)d_in[16];
    const float* m1_b   = (const float*)d_in[17];
    const float* m2_w   = (const float*)d_in[18];
    const float* m2_b   = (const float*)d_in[19];
    float* out = (float*)d_out;

    __half *detT, *aimT, *dx, *phx, *ax, *thx, *fm, *fT, *nap, *ndp;
    __half *gwr, *thwr, *phwr, *Wwr, *Qwr;
    float *nonaim, *pooled;
    cudaGetSymbolAddress((void**)&detT,   g_detT);
    cudaGetSymbolAddress((void**)&aimT,   g_aimT);
    cudaGetSymbolAddress((void**)&dx,     g_dx);
    cudaGetSymbolAddress((void**)&phx,    g_phx);
    cudaGetSymbolAddress((void**)&ax,     g_ax);
    cudaGetSymbolAddress((void**)&thx,    g_thx);
    cudaGetSymbolAddress((void**)&fm,     g_fm);
    cudaGetSymbolAddress((void**)&fT,     g_fT);
    cudaGetSymbolAddress((void**)&nap,    g_nap);
    cudaGetSymbolAddress((void**)&ndp,    g_ndp);
    cudaGetSymbolAddress((void**)&nonaim, g_nonaim);
    cudaGetSymbolAddress((void**)&pooled, g_pooled);
    cudaGetSymbolAddress((void**)&gwr,    g_gwr);
    cudaGetSymbolAddress((void**)&thwr,   g_thwr);
    cudaGetSymbolAddress((void**)&phwr,   g_phwr);
    cudaGetSymbolAddress((void**)&Wwr,    g_Wwr);
    cudaGetSymbolAddress((void**)&Qwr,    g_Qwr);

    const long offNonDet = 0;
    const long offActDet = (long)Bc * C * Nd;
    const long offActAim = 2 * offActDet;
    const long offCw     = offActAim + (long)Bc * C * Na;

    cudaFuncSetAttribute(mgemm,        cudaFuncAttributeMaxDynamicSharedMemorySize, GS128);
    cudaFuncSetAttribute(tgemm<0,128>, cudaFuncAttributeMaxDynamicSharedMemorySize, GS128);
    cudaFuncSetAttribute(tgemm<2,128>, cudaFuncAttributeMaxDynamicSharedMemorySize, GS128);
    cudaFuncSetAttribute(tgemm<0,64>,  cudaFuncAttributeMaxDynamicSharedMemorySize, GS64);
    cudaFuncSetAttribute(tgemm<1,64>,  cudaFuncAttributeMaxDynamicSharedMemorySize, GS64);

    const int n4 = (Ci * C) / 4;

    // prologue
    transpose_f2h_k<<<dim3(Nd / 32, C / 32, Bc), dim3(32, 8)>>>(detect, detT, C, Nd);
    transpose_f2h_k<<<dim3(Na / 32, C / 32, Bc), dim3(32, 8)>>>(aim,    aimT, C, Na);
    round5_k<<<dim3((n4 + 255) / 256, 5), 256>>>(
        g_w, th_w, ph_w, W_w, Q_w, gwr, thwr, phwr, Wwr, Qwr, n4);

    // MERGE1: G1 + G2 + G3 + G4 (uniform K=1024 -> no long-K tail)
    {
        GDesc4 P; P.n = 4;
        int off = 0;
        off += 18 * 4 * Bc;   // G1: dx[Ci,Nd] = gwr * detT^T + g_b[m]
        P.d[0] = { gwr, detT, dx, g_b, nullptr, 0, (long)Nd*C, (long)Ci*Nd,
                   C, Nd, 1, 18, 4, off, 1.f };
        off += 4 * 18 * Bc;   // G2: phx[Nd,Ci] = detT * phwr^T + ph_b[n]
        P.d[1] = { detT, phwr, phx, nullptr, ph_b, (long)Nd*C, 0, (long)Nd*Ci,
                   C, Ci, 2, 4, 18, off, 1.f };
        off += 2 * 4 * Bc;    // G3: ax[Ci,Na] = gwr * aimT^T + g_b[m]
        P.d[2] = { gwr, aimT, ax, g_b, nullptr, 0, (long)Na*C, (long)Ci*Na,
                   C, Na, 1, 2, 4, off, 1.f };
        off += 4 * 2 * Bc;    // G4: thx[Na,Ci] = aimT * thwr^T + th_b[n]
        P.d[3] = { aimT, thwr, thx, nullptr, th_b, (long)Na*C, 0, (long)Na*Ci,
                   C, Ci, 2, 4, 2, off, 1.f };
        mgemm<<<off, 256, GS128>>>(P);
    }

    // G5: f[Na,Nd] = theta * phi^T
    tgemm<0,128><<<dim3(Nd/128, Na/128, Bc), 256, GS128>>>(
        thx, phx, fm, Ci, Nd, (long)Na*Ci, (long)Nd*Ci, (long)Na*Nd, 1.f,
        nullptr, nullptr, nullptr, nullptr, 0, nullptr, nullptr);
    // T5b: fT = transpose(f)
    transpose_h_k<<<dim3(Nd / 32, Na / 32, Bc), dim3(32, 8)>>>(fm, fT, Na, Nd);

    // G7: ndp[Nd,Ci] = (1/Na) fT * ax^T   (NB=128, 576 CTAs, nk=16)
    tgemm<0,128><<<dim3(Ci/128, Nd/128, Bc), 256, GS128>>>(
        fT, ax, ndp, Na, Ci, (long)Nd*Na, (long)Ci*Na, (long)Nd*Ci, 1.f/Na,
        nullptr, nullptr, nullptr, nullptr, 0, nullptr, nullptr);
    // G6: nap[Na,Ci] = (1/Nd) f * dx^T    (NB=64, 128 CTAs, 3 CTAs/SM)
    tgemm<0,64><<<dim3(Ci/64, Na/128, Bc), 128, GS64>>>(
        fm, dx, nap, Nd, Ci, (long)Na*Nd, (long)Ci*Nd, (long)Na*Ci, 1.f/Nd,
        nullptr, nullptr, nullptr, nullptr, 0, nullptr, nullptr);

    // G8: non_aim[C,Na] = bn(Wwr * nap^T + W_b) + aim   (fp32 out)
    tgemm<1,64><<<dim3(Na/64, C/128, Bc), 128, GS64>>>(
        Wwr, nap, nonaim, Ci, Na, 0, (long)Na*Ci, (long)C*Na, 1.f,
        W_b, W_bn_g, W_bn_b, aim, (long)C*Na, nullptr, nullptr);
    // pool + gate
    pool_k<<<(Bc * C) / 8, 256>>>(nonaim, pooled);
    gate_k<<<Bc, 256>>>(pooled, m1_w, m1_b, m2_w, m2_b, out + offCw);
    // G9: non_det + act_det fused
    tgemm<2,128><<<dim3(Nd/128, C/128, Bc), 256, GS128>>>(
        Qwr, ndp, out + offNonDet, Ci, Nd, 0, (long)Nd*Ci, (long)C*Nd, 1.f,
        Q_b, Q_bn_g, Q_bn_b, detect, (long)C*Nd,
        out + offCw, out + offActDet);
    // act_aim = non_aim * cw
    const long t4a = (long)Bc * C * Na / 4;
    scale_k<<<(unsigned)((t4a + 255) / 256), 256>>>(
        nonaim, out + offCw, out + offActAim, Na / 4, t4a);
}